// round 17
// baseline (speedup 1.0000x reference)
#include <cuda_runtime.h>
#include <math_constants.h>

// InstanceAwarePointMatching — fused dual top-k (K=3) scatter, v4.
// Single-DRAM-read design: tile streamed through smem in 8 strips of 32 rows.
// Half A (t<256): column top-3 from smem. Half B: 8 threads/row, stride-8
// scan + 3-round shfl merge. __ldcs strip loads / __stcs zero fills keep L2
// clean. Bytes pinned at floor: 134MB read + 268MB write.
// out (floats): [0,PRS) = score_map, [PRS,2PRS) = corr_map (0.0/1.0).
// Masks arrive as int32. exp monotonic -> topk on raw x, exp winners only.
// Tie order inside top-3 does not affect output (scatter is set-valued).

#define SMEM_STRIDE 264   // 256 + 8: makes both column and stride-8 row reads conflict-free

static __device__ __forceinline__ void insert3_full(float v, int i,
                                                    float& v0, int& i0,
                                                    float& v1, int& i1,
                                                    float& v2, int& i2) {
    if (v > v0)      { v2 = v1; i2 = i1; v1 = v0; i1 = i0; v0 = v; i0 = i; }
    else if (v > v1) { v2 = v1; i2 = i1; v1 = v;  i1 = i; }
    else             { v2 = v;  i2 = i; }
}

#define TRY_INS(v, i, v0, i0, v1, i1, v2, i2) \
    do { if ((v) > (v2)) insert3_full((v), (i), v0, i0, v1, i1, v2, i2); } while (0)

__global__ __launch_bounds__(512, 4)
void pm_kernel(const float* __restrict__ x,     // [P,256,256]
               const int*   __restrict__ refm,  // [P,256] int32 bool
               const int*   __restrict__ srcm,  // [P,256] int32 bool
               float* __restrict__ out,          // [2*PRS] floats
               int PRS)
{
    const int p  = blockIdx.x;
    const int t  = threadIdx.x;       // 0..511
    const int tt = t & 255;

    __shared__ float         tile[32 * SMEM_STRIDE];
    __shared__ unsigned char s_refm[256];
    __shared__ unsigned char s_srcm[256];

    if (t < 256) {
        s_refm[t] = (unsigned char)(refm[p * 256 + t] != 0);
        s_srcm[t] = (unsigned char)(srcm[p * 256 + t] != 0);
    }

    // ---- zero this block's output slices (streaming stores) ----
    float* score = out;
    float* corr  = out + PRS;
    const size_t sbase = (size_t)p << 16;
    float4 z = make_float4(0.f, 0.f, 0.f, 0.f);
    float4* s4 = (float4*)(score + sbase);
    float4* c4 = (float4*)(corr  + sbase);
    #pragma unroll 8
    for (int k = t; k < 16384; k += 512) { __stcs(s4 + k, z); __stcs(c4 + k, z); }
    // (ordered before first scatter by the post-load __syncthreads in strip 0)

    const float* xp = x + sbase;
    float* sp = score + sbase;
    float* cp = corr  + sbase;

    // half A per-thread column top-3 state
    float v0 = -CUDART_INF_F, v1 = -CUDART_INF_F, v2 = -CUDART_INF_F;
    int   i0 = 0, i1 = 0, i2 = 0;

    const int sub  = tt & 7;    // half B: sub-scanner within row
    const int rloc = tt >> 3;   // half B: row within strip (0..31)

    #pragma unroll 1
    for (int strip = 0; strip < 8; ++strip) {
        // ---- load strip: 32 rows x 256 cols, 512 thr x 4 float4, coalesced ----
        const float4* g4 = (const float4*)(xp + strip * 32 * 256);
        #pragma unroll
        for (int q = 0; q < 4; ++q) {
            int idx  = t + q * 512;        // 0..2047 float4 slots
            int row  = idx >> 6;           // 64 float4 per row
            int col4 = idx & 63;
            float4 v = __ldcs(g4 + idx);
            *(float4*)&tile[row * SMEM_STRIDE + col4 * 4] = v;
        }
        __syncthreads();

        if (t < 256) {
            // ---- column tt: scan 32 rows of this strip ----
            #pragma unroll
            for (int j = 0; j < 32; ++j) {
                float v = tile[j * SMEM_STRIDE + tt];
                TRY_INS(v, strip * 32 + j, v0, i0, v1, i1, v2, i2);
            }
        } else {
            // ---- row rloc: 8 threads scan stride-8 columns, then merge ----
            float w0 = -CUDART_INF_F, w1 = -CUDART_INF_F, w2 = -CUDART_INF_F;
            int   j0 = 0, j1 = 0, j2 = 0;
            const float* rowp = &tile[rloc * SMEM_STRIDE];
            #pragma unroll
            for (int i = 0; i < 32; ++i) {
                int c = sub + 8 * i;
                float v = rowp[c];
                TRY_INS(v, c, w0, j0, w1, j1, w2, j2);
            }
            // butterfly merge across the 8 sub-scanners (warp-contiguous)
            #pragma unroll
            for (int off = 1; off <= 4; off <<= 1) {
                float o0 = __shfl_xor_sync(0xffffffffu, w0, off);
                float o1 = __shfl_xor_sync(0xffffffffu, w1, off);
                float o2 = __shfl_xor_sync(0xffffffffu, w2, off);
                int   q0 = __shfl_xor_sync(0xffffffffu, j0, off);
                int   q1 = __shfl_xor_sync(0xffffffffu, j1, off);
                int   q2 = __shfl_xor_sync(0xffffffffu, j2, off);
                TRY_INS(o0, q0, w0, j0, w1, j1, w2, j2);
                TRY_INS(o1, q1, w0, j0, w1, j1, w2, j2);
                TRY_INS(o2, q2, w0, j0, w1, j1, w2, j2);
            }
            if (sub == 0) {
                // scatter this row's winners (ref-direction top-k)
                int r = strip * 32 + rloc;
                bool rm = s_refm[r] != 0;
                int   cis[3] = {j0, j1, j2};
                float vs [3] = {w0, w1, w2};
                #pragma unroll
                for (int k = 0; k < 3; ++k) {
                    int c = cis[k];
                    float ev = __expf(vs[k]);
                    atomicAdd(&sp[r * 256 + c], 0.5f * ev);
                    if (ev > 0.0f && rm && s_srcm[c]) cp[r * 256 + c] = 1.0f;
                }
            }
        }
        __syncthreads();   // strip consumed before next overwrite
    }

    // ---- column winners: column tt, rows i0..2 (src-direction top-k) ----
    if (t < 256) {
        bool sm = s_srcm[tt] != 0;
        int   ris[3] = {i0, i1, i2};
        float vs [3] = {v0, v1, v2};
        #pragma unroll
        for (int k = 0; k < 3; ++k) {
            int r = ris[k];
            float ev = __expf(vs[k]);
            atomicAdd(&sp[r * 256 + tt], 0.5f * ev);
            if (ev > 0.0f && sm && s_refm[r]) cp[r * 256 + tt] = 1.0f;
        }
    }
}

extern "C" void kernel_launch(void* const* d_in, const int* in_sizes, int n_in,
                              void* d_out, int out_size) {
    const float* x    = (const float*)d_in[0];
    // d_in[1] = node_corr_scores (unused: conditional=False)
    const int*   refm = (const int*)d_in[2];
    const int*   srcm = (const int*)d_in[3];
    int P   = in_sizes[1];       // node_corr_scores has P elements
    int PRS = in_sizes[0];       // P*R*S

    pm_kernel<<<P, 512>>>(x, refm, srcm, (float*)d_out, PRS);
}